// round 16
// baseline (speedup 1.0000x reference)
#include <cuda_runtime.h>
#include <cstdint>

#define DIM 128
#define MAXN 50176
#define MAXE 600000
#define MAXNB 512
#define BM 128
#define BK 32
#define AP 36                   // padded smem row pitch (words), conflict-free
#define TILEW (BM * AP)         // 4608 words per tile buffer
#define SMEM_BYTES (4 * TILEW * 4)   // 73728 B (gemm)
#define BUCKET_SMEM 65536            // 128 rows x 512 B

__device__ float g_hpre[MAXN * DIM];       // x + agg
__device__ float g_h1[MAXN * DIM];         // Linear1 out (raw, pre-BN)
__device__ float g_stats[2 * DIM];         // colsum | colsumsq
__device__ unsigned g_w1[DIM * DIM];       // tf32-rounded weights
__device__ unsigned g_w2[DIM * DIM];
__device__ unsigned g_wres[DIM * DIM];
__device__ int g_hist[MAXNB];
__device__ int g_off[MAXNB + 1];
__device__ int g_cur[MAXNB];
__device__ unsigned g_edges[MAXE];         // (src<<7) | (dst & 127)

// ---------------------------------------------------------------------------
__device__ __forceinline__ unsigned f2tf(float f) {
    unsigned r;
    asm("cvt.rna.tf32.f32 %0, %1;" : "=r"(r) : "f"(f));
    return r;
}

__device__ __forceinline__ void mma_tf32(float* c, const unsigned* a, const unsigned* b) {
    asm volatile(
        "mma.sync.aligned.m16n8k8.row.col.f32.tf32.tf32.f32 "
        "{%0,%1,%2,%3}, {%4,%5,%6,%7}, {%8,%9}, {%0,%1,%2,%3};"
        : "+f"(c[0]), "+f"(c[1]), "+f"(c[2]), "+f"(c[3])
        : "r"(a[0]), "r"(a[1]), "r"(a[2]), "r"(a[3]), "r"(b[0]), "r"(b[1]));
}

__device__ __forceinline__ void cp16(unsigned smem_dst, const void* gsrc) {
    asm volatile("cp.async.ca.shared.global [%0], [%1], 16;"
                 :: "r"(smem_dst), "l"(gsrc));
}

__device__ __forceinline__ void ldsm4(unsigned& r0, unsigned& r1,
                                      unsigned& r2, unsigned& r3,
                                      const unsigned* p) {
    unsigned addr = (unsigned)__cvta_generic_to_shared(p);
    asm volatile("ldmatrix.sync.aligned.m8n8.x4.shared.b16 {%0,%1,%2,%3}, [%4];"
                 : "=r"(r0), "=r"(r1), "=r"(r2), "=r"(r3) : "r"(addr));
}

// ---------------------------------------------------------------------------
// K0: round weights ; zero stats + hist
// ---------------------------------------------------------------------------
__global__ void init_kernel(const float* __restrict__ W1,
                            const float* __restrict__ W2,
                            const float* __restrict__ Wres) {
    int gid = blockIdx.x * blockDim.x + threadIdx.x;
    if (gid < 2 * DIM) g_stats[gid] = 0.0f;
    if (gid < MAXNB) g_hist[gid] = 0;
    if (gid < DIM * DIM) {
        g_w1[gid]   = f2tf(W1[gid]);
        g_w2[gid]   = f2tf(W2[gid]);
        g_wres[gid] = f2tf(Wres[gid]);
    }
}

// ---------------------------------------------------------------------------
// K1: histogram of dst buckets
// ---------------------------------------------------------------------------
__global__ void hist_kernel(const int* __restrict__ ei, int E) {
    int e = blockIdx.x * blockDim.x + threadIdx.x;
    if (e < E) atomicAdd(&g_hist[ei[E + e] >> 7], 1);
}

// ---------------------------------------------------------------------------
// K2: single-block exclusive scan over NB (<=512) bins
// ---------------------------------------------------------------------------
__global__ __launch_bounds__(512, 1)
void scan_kernel(int NB) {
    __shared__ int wt[16];
    int t = threadIdx.x, lane = t & 31, w = t >> 5;
    int c = (t < NB) ? g_hist[t] : 0;
    int v = c;
#pragma unroll
    for (int o = 1; o < 32; o <<= 1) {
        int u = __shfl_up_sync(0xffffffff, v, o);
        if (lane >= o) v += u;
    }
    if (lane == 31) wt[w] = v;
    __syncthreads();
    if (w == 0) {
        int x2 = (lane < 16) ? wt[lane] : 0;
#pragma unroll
        for (int o = 1; o < 16; o <<= 1) {
            int u = __shfl_up_sync(0xffffffff, x2, o);
            if (lane >= o) x2 += u;
        }
        if (lane < 16) wt[lane] = x2;
    }
    __syncthreads();
    int excl = v - c + (w > 0 ? wt[w - 1] : 0);
    if (t < NB) { g_off[t] = excl; g_cur[t] = excl; }
    if (t == NB - 1) g_off[NB] = excl + c;
}

// ---------------------------------------------------------------------------
// K3: fill bucketed edge lists (packed records)
// ---------------------------------------------------------------------------
__global__ void fill_kernel(const int* __restrict__ ei, int E) {
    int e = blockIdx.x * blockDim.x + threadIdx.x;
    if (e < E) {
        int src = ei[e];
        int dst = ei[E + e];
        int b = dst >> 7;
        int pos = atomicAdd(&g_cur[b], 1);
        g_edges[pos] = ((unsigned)src << 7) | (unsigned)(dst & 127);
    }
}

// ---------------------------------------------------------------------------
// K4: bucket accumulate. CTA b owns rows [b*128, b*128+128).
// smem init = x rows (the GIN self term), warps own 16 rows each (exclusive,
// no atomics), ballot-filter over the bucket's edge list, write back once.
// ---------------------------------------------------------------------------
__global__ __launch_bounds__(256)
void bucket_kernel(const float* __restrict__ x, int M) {
    extern __shared__ float4 smf4[];        // [128][32]
    const int tid = threadIdx.x;
    const int w = tid >> 5;
    const int lane = tid & 31;
    const int b = blockIdx.x;
    const int row0 = b * BM;
    const int rows = min(BM, M - row0);

    // load x rows into smem via cp.async
    unsigned sbase = (unsigned)__cvta_generic_to_shared(smf4);
    for (int idx = tid; idx < rows * 32; idx += 256) {
        cp16(sbase + (unsigned)idx * 16,
             (const float4*)(x + (size_t)(row0 + (idx >> 5)) * DIM) + (idx & 31));
    }
    asm volatile("cp.async.commit_group;" ::: "memory");
    asm volatile("cp.async.wait_group 0;" ::: "memory");
    __syncthreads();

    const int beg = g_off[b];
    const int end = g_off[b + 1];
    for (int base = beg; base < end; base += 32) {
        int idx = base + lane;
        unsigned rec = (idx < end) ? g_edges[idx] : 0u;
        bool mine = (idx < end) && ((int)((rec & 127u) >> 4) == w);
        unsigned m = __ballot_sync(0xffffffff, mine);
        while (m) {
            int bit = __ffs(m) - 1;
            m &= m - 1;
            unsigned rr = __shfl_sync(0xffffffff, rec, bit);
            int r = (int)(rr & 127u);
            int s = (int)(rr >> 7);
            float4 v = __ldg((const float4*)(x + (size_t)s * DIM) + lane);
            float4* p = smf4 + r * 32 + lane;
            float4 c = *p;
            c.x += v.x; c.y += v.y; c.z += v.z; c.w += v.w;
            *p = c;
        }
    }
    __syncthreads();

    for (int idx = tid; idx < rows * 32; idx += 256) {
        ((float4*)g_hpre)[(size_t)(row0 + (idx >> 5)) * 32 + (idx & 31)] = smf4[idx];
    }
}

// ---------------------------------------------------------------------------
// Pipelined tf32 GEMM (frozen R8 config): 256 thr, 8 warps 4m x 2n, 32x64
// warp tiles, 2-stage cp.async + ldmatrix.
// PHASE 1: h1 = h_pre @ W1^T + b1 ; BN column sum/sumsq        (K=128)
// PHASE 2: out = lrelu_.2( bnlrelu(h1) @ W2^T + x @ Wres^T + b2 )  (K=256)
// ---------------------------------------------------------------------------
template <int PHASE>
__global__ __launch_bounds__(256, 2)
void gemm_kernel(const float* __restrict__ Ax,      // phase2: x
                 const float* __restrict__ bias,
                 const float* __restrict__ gamma,
                 const float* __restrict__ beta,
                 float* __restrict__ outp,
                 int M, float invM) {
    extern __shared__ unsigned smem[];
    unsigned* Abuf = smem;                 // [2][TILEW]
    unsigned* Wbuf = smem + 2 * TILEW;     // [2][TILEW]
    __shared__ float s_sum[DIM];
    __shared__ float s_sq[DIM];
    __shared__ float ssc[DIM];
    __shared__ float ssh[DIM];

    const int tid  = threadIdx.x;
    const int wid  = tid >> 5;
    const int lane = tid & 31;
    const int g    = lane >> 2;
    const int tg   = lane & 3;
    const int lm   = lane >> 3;
    const int lr   = lane & 7;
    const int wm   = wid & 3;
    const int wn   = wid >> 2;
    const int rowBase = blockIdx.x * BM;

    if (PHASE == 1) {
        if (tid < DIM) { s_sum[tid] = 0.f; s_sq[tid] = 0.f; }
    } else {
        if (tid < DIM) {
            float mu  = g_stats[tid] * invM;
            float var = g_stats[DIM + tid] * invM - mu * mu;
            float rstd = rsqrtf(var + 1e-5f);
            float s = gamma[tid] * rstd;
            ssc[tid] = s;
            ssh[tid] = beta[tid] - mu * s;
        }
    }

    const int NCHUNK = (PHASE == 1) ? 4 : 8;

    auto load_chunk = [&](int kc, int bufidx) {
        const int kbase = kc * BK;
        unsigned* Ad = Abuf + bufidx * TILEW;
        unsigned* Wd = Wbuf + bufidx * TILEW;
#pragma unroll
        for (int t = 0; t < 4; t++) {
            int idx = tid + t * 256;
            int m = idx >> 3;
            int f4 = (idx & 7) * 4;
            const void* asrc;
            if (PHASE == 1) {
                asrc = g_hpre + (size_t)(rowBase + m) * DIM + kbase + f4;
            } else if (kbase < DIM) {
                asrc = g_h1 + (size_t)(rowBase + m) * DIM + kbase + f4;
            } else {
                int gr = rowBase + m;
                if (gr >= M) gr = M - 1;
                asrc = Ax + (size_t)gr * DIM + (kbase - DIM) + f4;
            }
            cp16((unsigned)__cvta_generic_to_shared(Ad + m * AP + f4), asrc);
            const unsigned* wsrc;
            if (PHASE == 1)            wsrc = g_w1   + m * DIM + kbase + f4;
            else if (kbase < DIM)      wsrc = g_w2   + m * DIM + kbase + f4;
            else                       wsrc = g_wres + m * DIM + (kbase - DIM) + f4;
            cp16((unsigned)__cvta_generic_to_shared(Wd + m * AP + f4), wsrc);
        }
        asm volatile("cp.async.commit_group;" ::: "memory");
    };

    float acc[2][8][4];
#pragma unroll
    for (int i = 0; i < 2; i++)
#pragma unroll
        for (int j = 0; j < 8; j++)
#pragma unroll
            for (int r = 0; r < 4; r++) acc[i][j][r] = 0.f;

    load_chunk(0, 0);

#pragma unroll 1
    for (int kc = 0; kc < NCHUNK; kc++) {
        if (kc + 1 < NCHUNK) {
            load_chunk(kc + 1, (kc + 1) & 1);
            asm volatile("cp.async.wait_group 1;" ::: "memory");
        } else {
            asm volatile("cp.async.wait_group 0;" ::: "memory");
        }
        __syncthreads();

        unsigned* As = Abuf + (kc & 1) * TILEW;
        const unsigned* Ws = Wbuf + (kc & 1) * TILEW;

        if (PHASE == 2 && kc * BK < DIM) {
            const int kbase = kc * BK;
#pragma unroll
            for (int t = 0; t < 4; t++) {
                int idx = tid + t * 256;
                int m = idx >> 3;
                int f4 = (idx & 7) * 4;
                unsigned* p = As + m * AP + f4;
                float4 v = *(float4*)p;
                int kk = kbase + f4;
                v.x = fmaf(v.x, ssc[kk + 0], ssh[kk + 0]);
                v.y = fmaf(v.y, ssc[kk + 1], ssh[kk + 1]);
                v.z = fmaf(v.z, ssc[kk + 2], ssh[kk + 2]);
                v.w = fmaf(v.w, ssc[kk + 3], ssh[kk + 3]);
                v.x = v.x > 0.f ? v.x : 0.01f * v.x;
                v.y = v.y > 0.f ? v.y : 0.01f * v.y;
                v.z = v.z > 0.f ? v.z : 0.01f * v.z;
                v.w = v.w > 0.f ? v.w : 0.01f * v.w;
                p[0] = f2tf(v.x); p[1] = f2tf(v.y);
                p[2] = f2tf(v.z); p[3] = f2tf(v.w);
            }
            __syncthreads();
        }

#pragma unroll
        for (int k8 = 0; k8 < 4; k8++) {
            const int kof = k8 * 8;
            unsigned afrag[2][4];
#pragma unroll
            for (int mt = 0; mt < 2; mt++) {
                int r = wm * 32 + mt * 16 + (lm & 1) * 8 + lr;
                ldsm4(afrag[mt][0], afrag[mt][1], afrag[mt][2], afrag[mt][3],
                      As + r * AP + kof + (lm >> 1) * 4);
            }
            unsigned bfrag[8][2];
#pragma unroll
            for (int ntp = 0; ntp < 4; ntp++) {
                int n = wn * 64 + ntp * 16 + (lm >> 1) * 8 + lr;
                ldsm4(bfrag[2 * ntp][0], bfrag[2 * ntp][1],
                      bfrag[2 * ntp + 1][0], bfrag[2 * ntp + 1][1],
                      Ws + n * AP + kof + (lm & 1) * 4);
            }
#pragma unroll
            for (int mt = 0; mt < 2; mt++)
#pragma unroll
                for (int nt = 0; nt < 8; nt++)
                    mma_tf32(acc[mt][nt], afrag[mt], bfrag[nt]);
        }
        __syncthreads();
    }

    if (PHASE == 1) {
        float tsum[8][2], tsq[8][2];
#pragma unroll
        for (int nt = 0; nt < 8; nt++)
            tsum[nt][0] = tsum[nt][1] = tsq[nt][0] = tsq[nt][1] = 0.f;

#pragma unroll
        for (int mt = 0; mt < 2; mt++) {
#pragma unroll
            for (int half = 0; half < 2; half++) {
                int gr = rowBase + wm * 32 + mt * 16 + g + half * 8;
                if (gr < M) {
#pragma unroll
                    for (int nt = 0; nt < 8; nt++) {
                        int c = wn * 64 + nt * 8 + tg * 2;
                        float v0 = acc[mt][nt][half * 2 + 0] + __ldg(bias + c);
                        float v1 = acc[mt][nt][half * 2 + 1] + __ldg(bias + c + 1);
                        tsum[nt][0] += v0;  tsum[nt][1] += v1;
                        tsq[nt][0] += v0 * v0;  tsq[nt][1] += v1 * v1;
                        *(float2*)(g_h1 + (size_t)gr * DIM + c) = make_float2(v0, v1);
                    }
                }
            }
        }
#pragma unroll
        for (int nt = 0; nt < 8; nt++) {
#pragma unroll
            for (int h = 0; h < 2; h++) {
#pragma unroll
                for (int ofs = 4; ofs < 32; ofs <<= 1) {
                    tsum[nt][h] += __shfl_xor_sync(0xffffffff, tsum[nt][h], ofs);
                    tsq[nt][h]  += __shfl_xor_sync(0xffffffff, tsq[nt][h], ofs);
                }
            }
        }
        if (g == 0) {
#pragma unroll
            for (int nt = 0; nt < 8; nt++) {
                int c = wn * 64 + nt * 8 + tg * 2;
                atomicAdd(&s_sum[c],     tsum[nt][0]);
                atomicAdd(&s_sum[c + 1], tsum[nt][1]);
                atomicAdd(&s_sq[c],      tsq[nt][0]);
                atomicAdd(&s_sq[c + 1],  tsq[nt][1]);
            }
        }
        __syncthreads();
        if (tid < DIM) {
            atomicAdd(&g_stats[tid],       s_sum[tid]);
            atomicAdd(&g_stats[DIM + tid], s_sq[tid]);
        }
    } else {
#pragma unroll
        for (int mt = 0; mt < 2; mt++) {
#pragma unroll
            for (int half = 0; half < 2; half++) {
                int gr = rowBase + wm * 32 + mt * 16 + g + half * 8;
                if (gr < M) {
#pragma unroll
                    for (int nt = 0; nt < 8; nt++) {
                        int c = wn * 64 + nt * 8 + tg * 2;
                        float v0 = acc[mt][nt][half * 2 + 0] + __ldg(bias + c);
                        float v1 = acc[mt][nt][half * 2 + 1] + __ldg(bias + c + 1);
                        v0 = v0 > 0.f ? v0 : 0.2f * v0;
                        v1 = v1 > 0.f ? v1 : 0.2f * v1;
                        *(float2*)(outp + (size_t)gr * DIM + c) = make_float2(v0, v1);
                    }
                }
            }
        }
    }
}

// ---------------------------------------------------------------------------
extern "C" void kernel_launch(void* const* d_in, const int* in_sizes, int n_in,
                              void* d_out, int out_size) {
    const float* x     = (const float*)d_in[0];
    const int* ei      = (const int*)d_in[1];
    const float* W1    = (const float*)d_in[2];
    const float* b1    = (const float*)d_in[3];
    const float* gamma = (const float*)d_in[4];
    const float* beta  = (const float*)d_in[5];
    const float* W2    = (const float*)d_in[6];
    const float* b2    = (const float*)d_in[7];
    const float* Wres  = (const float*)d_in[8];
    float* out         = (float*)d_out;

    int M = in_sizes[0] / DIM;       // 50000
    int E = in_sizes[1] / 2;         // 600000
    int NB = (M + BM - 1) / BM;      // 391

    static int configured = 0;
    if (!configured) {
        cudaFuncSetAttribute(gemm_kernel<1>,
                             cudaFuncAttributeMaxDynamicSharedMemorySize, SMEM_BYTES);
        cudaFuncSetAttribute(gemm_kernel<2>,
                             cudaFuncAttributeMaxDynamicSharedMemorySize, SMEM_BYTES);
        cudaFuncSetAttribute(bucket_kernel,
                             cudaFuncAttributeMaxDynamicSharedMemorySize, BUCKET_SMEM);
        configured = 1;
    }

    init_kernel<<<(DIM * DIM + 255) / 256, 256>>>(W1, W2, Wres);
    hist_kernel<<<(E + 255) / 256, 256>>>(ei, E);
    scan_kernel<<<1, 512>>>(NB);
    fill_kernel<<<(E + 255) / 256, 256>>>(ei, E);
    bucket_kernel<<<NB, 256, BUCKET_SMEM>>>(x, M);

    float invM = 1.0f / (float)M;
    gemm_kernel<1><<<NB, 256, SMEM_BYTES>>>(nullptr, b1, nullptr, nullptr, nullptr, M, invM);
    gemm_kernel<2><<<NB, 256, SMEM_BYTES>>>(x, b2, gamma, beta, out, M, invM);
}

// round 17
// speedup vs baseline: 2.5255x; 2.5255x over previous
#include <cuda_runtime.h>
#include <cstdint>

#define DIM 128
#define MAXN 50176
#define BM 128
#define BK 32
#define AP 36                   // padded smem row pitch (words), conflict-free
#define TILEW (BM * AP)         // 4608 words per tile buffer
#define SMEM_BYTES (4 * TILEW * 4)   // 2 A bufs + 2 W bufs = 73728 B

__device__ float g_hpre[MAXN * DIM];       // x + agg
__device__ float g_h1[MAXN * DIM];         // Linear1 out (raw, pre-BN)
__device__ float g_stats[2 * DIM];         // colsum | colsumsq
__device__ unsigned g_w1[DIM * DIM];       // tf32-rounded weights
__device__ unsigned g_w2[DIM * DIM];
__device__ unsigned g_wres[DIM * DIM];

// ---------------------------------------------------------------------------
__device__ __forceinline__ unsigned f2tf(float f) {
    unsigned r;
    asm("cvt.rna.tf32.f32 %0, %1;" : "=r"(r) : "f"(f));
    return r;
}

__device__ __forceinline__ void mma_tf32(float* c, const unsigned* a, const unsigned* b) {
    asm volatile(
        "mma.sync.aligned.m16n8k8.row.col.f32.tf32.tf32.f32 "
        "{%0,%1,%2,%3}, {%4,%5,%6,%7}, {%8,%9}, {%0,%1,%2,%3};"
        : "+f"(c[0]), "+f"(c[1]), "+f"(c[2]), "+f"(c[3])
        : "r"(a[0]), "r"(a[1]), "r"(a[2]), "r"(a[3]), "r"(b[0]), "r"(b[1]));
}

__device__ __forceinline__ void cp16(unsigned smem_dst, const void* gsrc) {
    asm volatile("cp.async.ca.shared.global [%0], [%1], 16;"
                 :: "r"(smem_dst), "l"(gsrc));
}

__device__ __forceinline__ void ldsm4(unsigned& r0, unsigned& r1,
                                      unsigned& r2, unsigned& r3,
                                      const unsigned* p) {
    unsigned addr = (unsigned)__cvta_generic_to_shared(p);
    asm volatile("ldmatrix.sync.aligned.m8n8.x4.shared.b16 {%0,%1,%2,%3}, [%4];"
                 : "=r"(r0), "=r"(r1), "=r"(r2), "=r"(r3) : "r"(addr));
}

// ---------------------------------------------------------------------------
// init: copy x -> g_hpre ; round weights ; zero stats   (one launch)
// ---------------------------------------------------------------------------
__global__ void init_kernel(const float* __restrict__ x,
                            const float* __restrict__ W1,
                            const float* __restrict__ W2,
                            const float* __restrict__ Wres, int n4) {
    cudaTriggerProgrammaticLaunchCompletion();   // let scatter launch early
    int gid = blockIdx.x * blockDim.x + threadIdx.x;
    if (gid < 2 * DIM) g_stats[gid] = 0.0f;
    if (gid < DIM * DIM) {
        g_w1[gid]   = f2tf(W1[gid]);
        g_w2[gid]   = f2tf(W2[gid]);
        g_wres[gid] = f2tf(Wres[gid]);
    }
    if (gid < n4) ((float4*)g_hpre)[gid] = ((const float4*)x)[gid];
}

// ---------------------------------------------------------------------------
// scatter-add: warp per edge, lane = 4 floats -> LDG.128 + red.global.v4.f32
// PDL: loads (independent of init's g_hpre writes) issued BEFORE gridDepSync.
// ---------------------------------------------------------------------------
__global__ void scatter_kernel(const float* __restrict__ x,
                               const int* __restrict__ ei,
                               int n_edges) {
    int g = blockIdx.x * blockDim.x + threadIdx.x;
    int e = g >> 5;
    int lane = g & 31;
    if (e >= n_edges) { cudaGridDependencySynchronize(); return; }
    int src = ei[e];
    int dst = ei[n_edges + e];
    const float4* xs = (const float4*)(x + (size_t)src * DIM) + lane;
    float4* hd = (float4*)(g_hpre + (size_t)dst * DIM) + lane;
    float4 v = __ldg(xs);
    cudaGridDependencySynchronize();             // wait for init before RMW
    asm volatile("red.global.add.v4.f32 [%0], {%1, %2, %3, %4};"
                 :: "l"(hd), "f"(v.x), "f"(v.y), "f"(v.z), "f"(v.w)
                 : "memory");
}

// ---------------------------------------------------------------------------
// Pipelined tf32 GEMM (frozen R8 config): 256 thr, 8 warps 4m x 2n, 32x64
// warp tiles, 2-stage cp.async + ldmatrix.
// PHASE 1: h1 = h_pre @ W1^T + b1 ; BN column sum/sumsq        (K=128)
//          PDL: W tiles for chunks 0-1 prefetched before gridDepSync.
// PHASE 2: out = lrelu_.2( bnlrelu(h1) @ W2^T + x @ Wres^T + b2 )  (K=256)
// ---------------------------------------------------------------------------
template <int PHASE>
__global__ __launch_bounds__(256, 2)
void gemm_kernel(const float* __restrict__ Ax,      // phase2: x
                 const float* __restrict__ bias,
                 const float* __restrict__ gamma,
                 const float* __restrict__ beta,
                 float* __restrict__ outp,
                 int M, float invM) {
    extern __shared__ unsigned smem[];
    unsigned* Abuf = smem;                 // [2][TILEW]
    unsigned* Wbuf = smem + 2 * TILEW;     // [2][TILEW]
    __shared__ float s_sum[DIM];
    __shared__ float s_sq[DIM];
    __shared__ float ssc[DIM];
    __shared__ float ssh[DIM];

    const int tid  = threadIdx.x;
    const int wid  = tid >> 5;
    const int lane = tid & 31;
    const int g    = lane >> 2;
    const int tg   = lane & 3;
    const int lm   = lane >> 3;
    const int lr   = lane & 7;
    const int wm   = wid & 3;
    const int wn   = wid >> 2;
    const int rowBase = blockIdx.x * BM;

    const int NCHUNK = (PHASE == 1) ? 4 : 8;

    // ---- split chunk loaders (W independent of scatter; A dependent) ----
    auto load_W = [&](int kc, int bufidx) {
        const int kbase = kc * BK;
        unsigned* Wd = Wbuf + bufidx * TILEW;
#pragma unroll
        for (int t = 0; t < 4; t++) {
            int idx = tid + t * 256;
            int m = idx >> 3;
            int f4 = (idx & 7) * 4;
            const unsigned* wsrc;
            if (PHASE == 1)            wsrc = g_w1   + m * DIM + kbase + f4;
            else if (kbase < DIM)      wsrc = g_w2   + m * DIM + kbase + f4;
            else                       wsrc = g_wres + m * DIM + (kbase - DIM) + f4;
            cp16((unsigned)__cvta_generic_to_shared(Wd + m * AP + f4), wsrc);
        }
    };
    auto load_A = [&](int kc, int bufidx) {
        const int kbase = kc * BK;
        unsigned* Ad = Abuf + bufidx * TILEW;
#pragma unroll
        for (int t = 0; t < 4; t++) {
            int idx = tid + t * 256;
            int m = idx >> 3;
            int f4 = (idx & 7) * 4;
            const void* asrc;
            if (PHASE == 1) {
                asrc = g_hpre + (size_t)(rowBase + m) * DIM + kbase + f4;
            } else if (kbase < DIM) {
                asrc = g_h1 + (size_t)(rowBase + m) * DIM + kbase + f4;
            } else {
                int gr = rowBase + m;
                if (gr >= M) gr = M - 1;
                asrc = Ax + (size_t)gr * DIM + (kbase - DIM) + f4;
            }
            cp16((unsigned)__cvta_generic_to_shared(Ad + m * AP + f4), asrc);
        }
    };

    float acc[2][8][4];
#pragma unroll
    for (int i = 0; i < 2; i++)
#pragma unroll
        for (int j = 0; j < 8; j++)
#pragma unroll
            for (int r = 0; r < 4; r++) acc[i][j][r] = 0.f;

    // ---- prologue: W(0),W(1) -> [gridDepSync] -> A(0) c0, A(1) c1 ----
    load_W(0, 0);
    load_W(1, 1);
    if (PHASE == 1) cudaGridDependencySynchronize();   // scatter must finish
    load_A(0, 0);
    asm volatile("cp.async.commit_group;" ::: "memory");   // g0={W0,W1,A0}
    load_A(1, 1);
    asm volatile("cp.async.commit_group;" ::: "memory");   // g1={A1}

    if (PHASE == 1) {
        if (tid < DIM) { s_sum[tid] = 0.f; s_sq[tid] = 0.f; }
    } else {
        if (tid < DIM) {
            float mu  = g_stats[tid] * invM;
            float var = g_stats[DIM + tid] * invM - mu * mu;
            float rstd = rsqrtf(var + 1e-5f);
            float s = gamma[tid] * rstd;
            ssc[tid] = s;
            ssh[tid] = beta[tid] - mu * s;
        }
    }

#pragma unroll 1
    for (int kc = 0; kc < NCHUNK; kc++) {
        if (kc >= 1 && kc + 1 < NCHUNK) {
            load_W(kc + 1, (kc + 1) & 1);
            load_A(kc + 1, (kc + 1) & 1);
            asm volatile("cp.async.commit_group;" ::: "memory");
        }
        if (kc + 1 < NCHUNK) {
            asm volatile("cp.async.wait_group 1;" ::: "memory");
        } else {
            asm volatile("cp.async.wait_group 0;" ::: "memory");
        }
        __syncthreads();

        unsigned* As = Abuf + (kc & 1) * TILEW;
        const unsigned* Ws = Wbuf + (kc & 1) * TILEW;

        // ---- phase2, h1 chunks: BN + leaky + tf32-round in smem ----
        if (PHASE == 2 && kc * BK < DIM) {
            const int kbase = kc * BK;
#pragma unroll
            for (int t = 0; t < 4; t++) {
                int idx = tid + t * 256;
                int m = idx >> 3;
                int f4 = (idx & 7) * 4;
                unsigned* p = As + m * AP + f4;
                float4 v = *(float4*)p;
                int kk = kbase + f4;
                v.x = fmaf(v.x, ssc[kk + 0], ssh[kk + 0]);
                v.y = fmaf(v.y, ssc[kk + 1], ssh[kk + 1]);
                v.z = fmaf(v.z, ssc[kk + 2], ssh[kk + 2]);
                v.w = fmaf(v.w, ssc[kk + 3], ssh[kk + 3]);
                v.x = v.x > 0.f ? v.x : 0.01f * v.x;
                v.y = v.y > 0.f ? v.y : 0.01f * v.y;
                v.z = v.z > 0.f ? v.z : 0.01f * v.z;
                v.w = v.w > 0.f ? v.w : 0.01f * v.w;
                p[0] = f2tf(v.x); p[1] = f2tf(v.y);
                p[2] = f2tf(v.z); p[3] = f2tf(v.w);
            }
            __syncthreads();
        }

#pragma unroll
        for (int k8 = 0; k8 < 4; k8++) {
            const int kof = k8 * 8;
            unsigned afrag[2][4];
#pragma unroll
            for (int mt = 0; mt < 2; mt++) {
                int r = wm * 32 + mt * 16 + (lm & 1) * 8 + lr;
                ldsm4(afrag[mt][0], afrag[mt][1], afrag[mt][2], afrag[mt][3],
                      As + r * AP + kof + (lm >> 1) * 4);
            }
            unsigned bfrag[8][2];
#pragma unroll
            for (int ntp = 0; ntp < 4; ntp++) {
                int n = wn * 64 + ntp * 16 + (lm >> 1) * 8 + lr;
                ldsm4(bfrag[2 * ntp][0], bfrag[2 * ntp][1],
                      bfrag[2 * ntp + 1][0], bfrag[2 * ntp + 1][1],
                      Ws + n * AP + kof + (lm & 1) * 4);
            }
#pragma unroll
            for (int mt = 0; mt < 2; mt++)
#pragma unroll
                for (int nt = 0; nt < 8; nt++)
                    mma_tf32(acc[mt][nt], afrag[mt], bfrag[nt]);
        }
        __syncthreads();
    }

    // ---- epilogue ----
    if (PHASE == 1) {
        float tsum[8][2], tsq[8][2];
#pragma unroll
        for (int nt = 0; nt < 8; nt++)
            tsum[nt][0] = tsum[nt][1] = tsq[nt][0] = tsq[nt][1] = 0.f;

#pragma unroll
        for (int mt = 0; mt < 2; mt++) {
#pragma unroll
            for (int half = 0; half < 2; half++) {
                int gr = rowBase + wm * 32 + mt * 16 + g + half * 8;
                if (gr < M) {
#pragma unroll
                    for (int nt = 0; nt < 8; nt++) {
                        int c = wn * 64 + nt * 8 + tg * 2;
                        float v0 = acc[mt][nt][half * 2 + 0] + __ldg(bias + c);
                        float v1 = acc[mt][nt][half * 2 + 1] + __ldg(bias + c + 1);
                        tsum[nt][0] += v0;  tsum[nt][1] += v1;
                        tsq[nt][0] += v0 * v0;  tsq[nt][1] += v1 * v1;
                        *(float2*)(g_h1 + (size_t)gr * DIM + c) = make_float2(v0, v1);
                    }
                }
            }
        }
#pragma unroll
        for (int nt = 0; nt < 8; nt++) {
#pragma unroll
            for (int h = 0; h < 2; h++) {
#pragma unroll
                for (int ofs = 4; ofs < 32; ofs <<= 1) {
                    tsum[nt][h] += __shfl_xor_sync(0xffffffff, tsum[nt][h], ofs);
                    tsq[nt][h]  += __shfl_xor_sync(0xffffffff, tsq[nt][h], ofs);
                }
            }
        }
        if (g == 0) {
#pragma unroll
            for (int nt = 0; nt < 8; nt++) {
                int c = wn * 64 + nt * 8 + tg * 2;
                atomicAdd(&s_sum[c],     tsum[nt][0]);
                atomicAdd(&s_sum[c + 1], tsum[nt][1]);
                atomicAdd(&s_sq[c],      tsq[nt][0]);
                atomicAdd(&s_sq[c + 1],  tsq[nt][1]);
            }
        }
        __syncthreads();
        if (tid < DIM) {
            atomicAdd(&g_stats[tid],       s_sum[tid]);
            atomicAdd(&g_stats[DIM + tid], s_sq[tid]);
        }
    } else {
#pragma unroll
        for (int mt = 0; mt < 2; mt++) {
#pragma unroll
            for (int half = 0; half < 2; half++) {
                int gr = rowBase + wm * 32 + mt * 16 + g + half * 8;
                if (gr < M) {
#pragma unroll
                    for (int nt = 0; nt < 8; nt++) {
                        int c = wn * 64 + nt * 8 + tg * 2;
                        float v0 = acc[mt][nt][half * 2 + 0] + __ldg(bias + c);
                        float v1 = acc[mt][nt][half * 2 + 1] + __ldg(bias + c + 1);
                        v0 = v0 > 0.f ? v0 : 0.2f * v0;
                        v1 = v1 > 0.f ? v1 : 0.2f * v1;
                        *(float2*)(outp + (size_t)gr * DIM + c) = make_float2(v0, v1);
                    }
                }
            }
        }
    }
}

// ---------------------------------------------------------------------------
extern "C" void kernel_launch(void* const* d_in, const int* in_sizes, int n_in,
                              void* d_out, int out_size) {
    const float* x     = (const float*)d_in[0];
    const int* ei      = (const int*)d_in[1];
    const float* W1    = (const float*)d_in[2];
    const float* b1    = (const float*)d_in[3];
    const float* gamma = (const float*)d_in[4];
    const float* beta  = (const float*)d_in[5];
    const float* W2    = (const float*)d_in[6];
    const float* b2    = (const float*)d_in[7];
    const float* Wres  = (const float*)d_in[8];
    float* out         = (float*)d_out;

    int M = in_sizes[0] / DIM;       // 50000
    int E = in_sizes[1] / 2;         // 600000
    int n4 = M * (DIM / 4);

    static int configured = 0;
    if (!configured) {
        cudaFuncSetAttribute(gemm_kernel<1>,
                             cudaFuncAttributeMaxDynamicSharedMemorySize, SMEM_BYTES);
        cudaFuncSetAttribute(gemm_kernel<2>,
                             cudaFuncAttributeMaxDynamicSharedMemorySize, SMEM_BYTES);
        configured = 1;
    }

    init_kernel<<<(n4 + 255) / 256, 256>>>(x, W1, W2, Wres, n4);

    // PDL launch attribute (programmatic serialization w/ previous kernel)
    cudaLaunchAttribute attrs[1];
    attrs[0].id = cudaLaunchAttributeProgrammaticStreamSerialization;
    attrs[0].val.programmaticStreamSerializationAllowed = 1;

    {
        long long work = (long long)E * 32;
        int blocks = (int)((work + 255) / 256);
        cudaLaunchConfig_t cfg = {};
        cfg.gridDim = dim3((unsigned)blocks);
        cfg.blockDim = dim3(256);
        cfg.attrs = attrs;
        cfg.numAttrs = 1;
        cudaLaunchKernelEx(&cfg, scatter_kernel, x, ei, E);
    }

    int gb = (M + BM - 1) / BM;
    float invM = 1.0f / (float)M;
    {
        cudaLaunchConfig_t cfg = {};
        cfg.gridDim = dim3((unsigned)gb);
        cfg.blockDim = dim3(256);
        cfg.dynamicSmemBytes = SMEM_BYTES;
        cfg.attrs = attrs;
        cfg.numAttrs = 1;
        cudaLaunchKernelEx(&cfg, gemm_kernel<1>,
                           (const float*)nullptr, b1,
                           (const float*)nullptr, (const float*)nullptr,
                           (float*)nullptr, M, invM);
    }
    gemm_kernel<2><<<gb, 256, SMEM_BYTES>>>(x, b2, gamma, beta, out, M, invM);
}